// round 5
// baseline (speedup 1.0000x reference)
#include <cuda_runtime.h>
#include <cstdint>

// ---------------------------------------------------------------------------
// RowLSTM: x(16,64,64,64), Wi(512,64,1,3), bi(512), Wh(512,128), bh(512)
// out: (16,128,64,64) fp32
// ---------------------------------------------------------------------------

#define B_  16
#define C_  64
#define H_  64
#define W_  64
#define HID_ 128
#define G_  512   // 4*HID
#define K_  192   // C_*3

static __device__ float g_i2h[(size_t)H_ * B_ * W_ * G_];   // 134 MB [h][b][w][g]
static __device__ float g_WiT[(size_t)K_ * G_];             // [k][g]
static __device__ float g_WhT[(size_t)HID_ * G_];           // [k][g]

__device__ __forceinline__ float sigmf(float v) {
    return __fdividef(1.0f, 1.0f + __expf(-v));
}
__device__ __forceinline__ float tanhf_(float v) {
    return __fdividef(2.0f, 1.0f + __expf(-2.0f * v)) - 1.0f;
}

// ---- f32x2 helpers ----------------------------------------------------------
__device__ __forceinline__ uint64_t pk2(float a, float b) {
    uint64_t r; asm("mov.b64 %0,{%1,%2};" : "=l"(r) : "f"(a), "f"(b)); return r;
}
__device__ __forceinline__ void upk2(uint64_t v, float& a, float& b) {
    asm("mov.b64 {%0,%1},%2;" : "=f"(a), "=f"(b) : "l"(v));
}
__device__ __forceinline__ uint64_t ffma2(uint64_t a, uint64_t b, uint64_t c) {
    uint64_t d; asm("fma.rn.f32x2 %0,%1,%2,%3;" : "=l"(d) : "l"(a), "l"(b), "l"(c)); return d;
}

// ---------------------------------------------------------------------------
// Kernel 0: transpose Wi -> WiT[k][g], Wh -> WhT[k][g]
// ---------------------------------------------------------------------------
__global__ void prep_kernel(const float* __restrict__ Wi, const float* __restrict__ Wh)
{
    int g = threadIdx.x;
    if (blockIdx.x < K_) {
        int k = blockIdx.x;
        g_WiT[(size_t)k * G_ + g] = Wi[(size_t)g * K_ + k];
    } else {
        int k = blockIdx.x - K_;
        g_WhT[(size_t)k * G_ + g] = Wh[(size_t)g * HID_ + k];
    }
}

// ---------------------------------------------------------------------------
// Kernel A: i2h GEMM. Grid 2048 = (b, h, gate-half). 512 threads.
// thread: 8 gates (g0l=(tid&31)*8 in 256-gate half), 4 cols (w0=(tid>>5)*4)
// Gate-pair packed f32x2 accumulators.
// ---------------------------------------------------------------------------
__global__ void __launch_bounds__(512, 2)
i2h_kernel(const float* __restrict__ x,
           const float* __restrict__ bi, const float* __restrict__ bh)
{
    const int b  = blockIdx.x & 15;
    const int h  = (blockIdx.x >> 4) & 63;
    const int gh = blockIdx.x >> 10;        // 0/1 gate half
    const int tid = threadIdx.x;
    const int gbase = gh * 256;

    __shared__ float xs[C_][68];       // [c][w+1], zero pad ends
    __shared__ float ws[12][256];      // Wi chunk [kk][g-local]

    for (int idx = tid; idx < C_ * W_; idx += 512) {
        int c = idx >> 6, w = idx & 63;
        xs[c][w + 1] = x[((((size_t)b * C_) + c) * H_ + h) * W_ + w];
    }
    if (tid < C_) { xs[tid][0] = 0.f; xs[tid][65] = 0.f; xs[tid][66] = 0.f; xs[tid][67] = 0.f; }

    const int g0l = (tid & 31) * 8;    // local gate base (8 gates)
    const int w0  = (tid >> 5) * 4;    // 4 cols

    uint64_t acc[4][4];                // [gate-pair][col]
#pragma unroll
    for (int i = 0; i < 4; i++)
#pragma unroll
        for (int j = 0; j < 4; j++) acc[i][j] = 0ull;

    for (int kc = 0; kc < 16; kc++) {
        __syncthreads();
#pragma unroll
        for (int u = 0; u < 6; u++) {
            int idx = tid + u * 512;
            int j = idx >> 8, g = idx & 255;
            ws[j][g] = g_WiT[((size_t)kc * 12 + j) * G_ + gbase + g];
        }
        __syncthreads();

#pragma unroll
        for (int cc = 0; cc < 4; cc++) {
            const int c = kc * 4 + cc;
            float4 xa = *reinterpret_cast<const float4*>(&xs[c][w0]);
            float2 xb = *reinterpret_cast<const float2*>(&xs[c][w0 + 4]);
            uint64_t xd[6];
            xd[0] = pk2(xa.x, xa.x); xd[1] = pk2(xa.y, xa.y);
            xd[2] = pk2(xa.z, xa.z); xd[3] = pk2(xa.w, xa.w);
            xd[4] = pk2(xb.x, xb.x); xd[5] = pk2(xb.y, xb.y);
#pragma unroll
            for (int kw = 0; kw < 3; kw++) {
                const ulonglong2 wp = *reinterpret_cast<const ulonglong2*>(&ws[cc * 3 + kw][g0l]);
                const ulonglong2 wq = *reinterpret_cast<const ulonglong2*>(&ws[cc * 3 + kw][g0l + 4]);
#pragma unroll
                for (int j = 0; j < 4; j++) {
                    uint64_t xv = xd[j + kw];
                    acc[0][j] = ffma2(wp.x, xv, acc[0][j]);
                    acc[1][j] = ffma2(wp.y, xv, acc[1][j]);
                    acc[2][j] = ffma2(wq.x, xv, acc[2][j]);
                    acc[3][j] = ffma2(wq.y, xv, acc[3][j]);
                }
            }
        }
    }

    const int g0 = gbase + g0l;
    float bias[8];
#pragma unroll
    for (int i = 0; i < 8; i++) bias[i] = bi[g0 + i] + bh[g0 + i];

    const size_t obase = ((((size_t)h * B_ + b) * W_) + w0) * G_ + g0;
#pragma unroll
    for (int j = 0; j < 4; j++) {
        float o0, o1, o2, o3, o4, o5, o6, o7;
        upk2(acc[0][j], o0, o1);
        upk2(acc[1][j], o2, o3);
        upk2(acc[2][j], o4, o5);
        upk2(acc[3][j], o6, o7);
        float4 v0 = make_float4(o0 + bias[0], o1 + bias[1], o2 + bias[2], o3 + bias[3]);
        float4 v1 = make_float4(o4 + bias[4], o5 + bias[5], o6 + bias[6], o7 + bias[7]);
        *reinterpret_cast<float4*>(&g_i2h[obase + (size_t)j * G_])     = v0;
        *reinterpret_cast<float4*>(&g_i2h[obase + (size_t)j * G_ + 4]) = v1;
    }
}

// ---------------------------------------------------------------------------
// Kernel B: recurrent scan. 128 blocks = (b, w-group of 8 cols), 512 threads.
// thread: gate-quad q = t&127 (gates 4q..4q+3), col-pair ch = t>>7 (cols 2ch,2ch+1)
// Gate-pair packed f32x2; h kept DUPLICATED in smem -> (h,h) u64 broadcast loads.
// ---------------------------------------------------------------------------
#define HDS 18   // hdup row stride (floats): 8 cols x 2 dup + pad 2 (keeps 8B align)
#define CBS 9    // cbuf row stride

__global__ void __launch_bounds__(512, 1)
rec_kernel(float* __restrict__ out)
{
    const int b  = blockIdx.x >> 3;
    const int w0 = (blockIdx.x & 7) * 8;
    const int t  = threadIdx.x;
    const int q  = t & 127;
    const int ch = t >> 7;          // 0..3

    __shared__ float hdup[HID_ * HDS];   // [k][2*col{dup}]
    __shared__ float cbuf[HID_ * CBS];   // [d][col]
    __shared__ float gbuf[8][G_];        // [col][gate]

    for (int p = t; p < HID_ * HDS; p += 512) hdup[p] = 0.f;
    for (int p = t; p < HID_ * CBS; p += 512) cbuf[p] = 0.f;
    __syncthreads();

    const ulonglong2* __restrict__ WhT2 = reinterpret_cast<const ulonglong2*>(g_WhT);

    for (int row = 0; row < H_; row++) {
        // i2h gate init loads issued early (gates 4q..4q+3, cols 2ch/2ch+1)
        const size_t ibase = ((((size_t)row * B_ + b) * W_) + w0 + 2 * ch) * G_ + 4 * q;
        float4 gv0 = *reinterpret_cast<const float4*>(&g_i2h[ibase]);
        float4 gv1 = *reinterpret_cast<const float4*>(&g_i2h[ibase + G_]);

        uint64_t a0c0 = 0ull, a1c0 = 0ull;   // gate pairs (4q,4q+1),(4q+2,4q+3) col 2ch
        uint64_t a0c1 = 0ull, a1c1 = 0ull;   // same, col 2ch+1

#pragma unroll 4
        for (int k = 0; k < HID_; k++) {
            ulonglong2 wp = __ldg(&WhT2[(size_t)k * (G_ / 4) + q]);
            uint64_t h0 = *reinterpret_cast<const uint64_t*>(&hdup[k * HDS + 4 * ch]);
            uint64_t h1 = *reinterpret_cast<const uint64_t*>(&hdup[k * HDS + 4 * ch + 2]);
            a0c0 = ffma2(wp.x, h0, a0c0);
            a1c0 = ffma2(wp.y, h0, a1c0);
            a0c1 = ffma2(wp.x, h1, a0c1);
            a1c1 = ffma2(wp.y, h1, a1c1);
        }

        {
            float s0, s1, s2, s3;
            upk2(a0c0, s0, s1); upk2(a1c0, s2, s3);
            *reinterpret_cast<float4*>(&gbuf[2 * ch][4 * q]) =
                make_float4(s0 + gv0.x, s1 + gv0.y, s2 + gv0.z, s3 + gv0.w);
            upk2(a0c1, s0, s1); upk2(a1c1, s2, s3);
            *reinterpret_cast<float4*>(&gbuf[2 * ch + 1][4 * q]) =
                make_float4(s0 + gv1.x, s1 + gv1.y, s2 + gv1.z, s3 + gv1.w);
        }
        __syncthreads();

        // pointwise: 1024 (col,d) pairs / 512 threads (2 each), fused out-write
#pragma unroll
        for (int pp = 0; pp < 2; pp++) {
            int p   = t + pp * 512;
            int col = p >> 7;
            int d   = p & 127;
            float ig = gbuf[col][d];
            float fg = gbuf[col][HID_ + d];
            float og = gbuf[col][2 * HID_ + d];
            float gg = gbuf[col][3 * HID_ + d];
            float cv = sigmf(fg) * cbuf[d * CBS + col] + sigmf(ig) * tanhf_(gg);
            float hv = sigmf(og) * tanhf_(cv);
            cbuf[d * CBS + col] = cv;
            *reinterpret_cast<float2*>(&hdup[d * HDS + 2 * col]) = make_float2(hv, hv);
            out[((((size_t)b * HID_ + d) * H_) + row) * W_ + w0 + col] = hv;
        }
        __syncthreads();
    }
}

// ---------------------------------------------------------------------------
extern "C" void kernel_launch(void* const* d_in, const int* in_sizes, int n_in,
                              void* d_out, int out_size)
{
    (void)in_sizes; (void)n_in; (void)out_size;
    const float* x  = (const float*)d_in[0];
    const float* Wi = (const float*)d_in[1];
    const float* bi = (const float*)d_in[2];
    const float* Wh = (const float*)d_in[3];
    const float* bh = (const float*)d_in[4];
    float* out = (float*)d_out;

    prep_kernel<<<K_ + HID_, G_>>>(Wi, Wh);
    i2h_kernel<<<B_ * H_ * 2, 512>>>(x, bi, bh);
    rec_kernel<<<B_ * (W_ / 8), 512>>>(out);
}